// round 11
// baseline (speedup 1.0000x reference)
#include <cuda_runtime.h>
#include <cstdint>

#define NB    4096     // batch
#define NO    256      // orbitals
#define NF    128      // fermions
#define HID   512      // hidden
#define LDA   132      // padded row stride: 528B, 16B-aligned
#define NTHR  256
#define PB    8        // LU panel width
#define NPAN  (NF/PB)  // 16 panels

// Shared layout (floats): A | idx | perm | pcopy | wcnt(8) | sJ(8)
#define SMEM_FLOATS (NF*LDA + NF + NF + NF + 8 + 8)
#define SMEM_BYTES  (SMEM_FLOATS * 4)

__device__ __forceinline__ void fma4(float4& a, float m, const float4& u) {
    a.x -= m * u.x; a.y -= m * u.y; a.z -= m * u.z; a.w -= m * u.w;
}

// Warp-synchronous panel factorization (warp 0 only). Factors panel columns
// [kp, kp+PB) over logical rows >= kp, virtual pivoting via perm.
__device__ __forceinline__ void factor_panel(float* __restrict__ A,
                                             int*   __restrict__ perm,
                                             int kp, int lane, float& logabs)
{
    #pragma unroll
    for (int kk = 0; kk < PB; kk++) {
        const int k = kp + kk;
        float v = -1.0f; int vi = k;
        #pragma unroll
        for (int j = 0; j < 4; j++) {
            const int i = lane + 32*j;
            if (i >= k) {
                const float a = fabsf(A[perm[i]*LDA + k]);
                if (a > v) { v = a; vi = i; }
            }
        }
        #pragma unroll
        for (int o = 16; o; o >>= 1) {
            const float ov = __shfl_xor_sync(0xffffffffu, v,  o);
            const int   oi = __shfl_xor_sync(0xffffffffu, vi, o);
            if (ov > v) { v = ov; vi = oi; }
        }
        int pk = 0; float inv = 0.0f;
        if (lane == 0) {
            if (vi != k) { int t = perm[k]; perm[k] = perm[vi]; perm[vi] = t; }
            pk = perm[k];
            const float piv = A[pk*LDA + k];
            logabs += __logf(fabsf(piv));
            inv = 1.0f / piv;
        }
        __syncwarp();
        pk  = __shfl_sync(0xffffffffu, pk,  0);
        inv = __shfl_sync(0xffffffffu, inv, 0);

        const float* prow = A + pk*LDA + kp;
        #pragma unroll
        for (int j = 0; j < 4; j++) {
            const int i = lane + 32*j;
            if (i > k) {
                float* row = A + perm[i]*LDA;
                const float m = row[k] * inv;
                row[k] = m;
                #pragma unroll
                for (int c = 0; c < PB; c++)
                    if (c > kk) row[kp + c] -= m * prow[c];
            }
        }
        __syncwarp();
    }
}

__global__ void __launch_bounds__(NTHR, 3)
lnjs_kernel(const float* __restrict__ n_in,
            const float* __restrict__ M_in,
            const float* __restrict__ W_in,
            const float* __restrict__ b_in,
            float* __restrict__ out)
{
    extern __shared__ float sm[];
    float* A     = sm;
    int*   idx   = (int*)(sm + NF*LDA);
    int*   perm  = idx + NF;
    int*   pcopy = perm + NF;
    int*   wcnt  = pcopy + NF;
    float* sJ    = (float*)(wcnt + 8);

    const int s    = blockIdx.x;
    const int tid  = threadIdx.x;
    const int lane = tid & 31;
    const int wid  = tid >> 5;

    // ---------- 1. occupied indices via ballot prefix (NO == NTHR == 256) ----------
    const float nv = n_in[s*NO + tid];
    const bool occ = nv > 0.5f;
    const unsigned mask = __ballot_sync(0xffffffffu, occ);
    const int rank = __popc(mask & ((1u << lane) - 1u));
    if (lane == 0) { wcnt[wid] = __popc(mask); sJ[wid] = 0.0f; }
    __syncthreads();
    {
        int off = 0;
        #pragma unroll
        for (int w = 0; w < 8; w++) if (w < wid) off += wcnt[w];
        if (occ) idx[off + rank] = tid;
    }
    if (tid < NF) perm[tid] = tid;
    __syncthreads();

    // ---------- 2. load A = M[idx] into smem (float4) ----------
    #pragma unroll
    for (int e = tid; e < NF*32; e += NTHR) {
        const int r  = e >> 5;
        const int c4 = e & 31;
        ((float4*)(A + r*LDA))[c4] = ((const float4*)(M_in + (size_t)idx[r]*NF))[c4];
    }
    __syncthreads();

    // ---------- 3. prologue: warp 0 factors panel 0 | warps 1-7 do Jastrow ----------
    float logabs = 0.0f;   // warp 0 lane 0 accumulates

    if (wid == 0) {
        factor_panel(A, perm, 0, lane, logabs);
    } else {
        float jl = 0.0f;
        for (int h = tid - 32; h < HID; h += 224) {
            float acc = b_in[h];
            #pragma unroll 4
            for (int i = 0; i < NF; i++)
                acc += W_in[(size_t)idx[i]*HID + h];
            jl += tanhf(acc);
        }
        #pragma unroll
        for (int o = 16; o; o >>= 1) jl += __shfl_xor_sync(0xffffffffu, jl, o);
        if (lane == 0) sJ[wid] = jl;
    }
    __syncthreads();

    // ---------- 4. blocked LU, lookahead-1, U materialized in place ----------
    for (int p = 0; p < NPAN - 1; p++) {
        const int kp = p * PB;
        const int pe = kp + PB;

        // ======== phase A ========
        // snapshot perm[pe..NF) for phase-B wide warps (warp 0 mutates perm in B)
        if (pe + tid < NF) pcopy[pe + tid] = perm[pe + tid];

        if (wid < 4) {
            // TRSM-materialize U of panel p, cols >= pe+8, written back in place.
            // One float4 column-group per thread; chain over the 8 pivot rows.
            const int g = ((pe + PB) >> 2) + (wid << 5) + lane;
            if (g < 32) {
                float4 u4[PB];
                #pragma unroll
                for (int k2 = 0; k2 < PB; k2++) {
                    float* ur = A + perm[kp + k2]*LDA;     // broadcast row ptr
                    float4 val = ((const float4*)ur)[g];
                    #pragma unroll
                    for (int j2 = 0; j2 < PB; j2++)
                        if (j2 < k2) fma4(val, ur[kp + j2], u4[j2]);
                    u4[k2] = val;
                    ((float4*)ur)[g] = val;
                }
            }
        } else {
            // strip update: cols [pe, pe+8), rows logical >= pe (on-the-fly TRSM)
            const int ch = (lane & 1) * 4;   // half of the 8-col strip
            const int rs = lane >> 1;        // 0..15
            float4 u4s[PB];
            #pragma unroll
            for (int k2 = 0; k2 < PB; k2++) {
                const float* ur = A + perm[kp + k2]*LDA;
                float4 val = *(const float4*)(ur + pe + ch);
                #pragma unroll
                for (int j2 = 0; j2 < PB; j2++)
                    if (j2 < k2) fma4(val, ur[kp + j2], u4s[j2]);
                u4s[k2] = val;
            }
            for (int i = pe + ((wid - 4) << 4) + rs; i < NF; i += 64) {
                float* row = A + perm[i]*LDA;
                const float4 l0 = *(const float4*)(row + kp);
                const float4 l1 = *(const float4*)(row + kp + 4);
                float4 a = *(const float4*)(row + pe + ch);
                fma4(a, l0.x, u4s[0]); fma4(a, l0.y, u4s[1]);
                fma4(a, l0.z, u4s[2]); fma4(a, l0.w, u4s[3]);
                fma4(a, l1.x, u4s[4]); fma4(a, l1.y, u4s[5]);
                fma4(a, l1.z, u4s[6]); fma4(a, l1.w, u4s[7]);
                *(float4*)(row + pe + ch) = a;
            }
        }
        __syncthreads();

        // ======== phase B: warp 0 factors panel p+1 | warps 1-7 wide update ========
        if (wid == 0) {
            factor_panel(A, perm, pe, lane, logabs);
        } else if (pe + PB < NF) {
            const bool act = (4*lane >= pe + PB);
            // U is materialized: straight loads, no TRSM chain.
            float4 u4[PB];
            if (act) {
                #pragma unroll
                for (int k2 = 0; k2 < PB; k2++)
                    u4[k2] = ((const float4*)(A + perm[kp + k2]*LDA))[lane];
            }
            // rows, 2-way unrolled for MLP
            for (int i = pe + (wid - 1); i < NF; i += 14) {
                const int ib = i + 7;
                const bool hb = ib < NF;
                float* rowa = A + pcopy[i]*LDA;
                float* rowb = hb ? (A + pcopy[ib]*LDA) : rowa;
                const float4 l0a = *(const float4*)(rowa + kp);
                const float4 l1a = *(const float4*)(rowa + kp + 4);
                const float4 l0b = *(const float4*)(rowb + kp);
                const float4 l1b = *(const float4*)(rowb + kp + 4);
                if (act) {
                    float4 a = *(const float4*)(rowa + 4*lane);
                    float4 b = *(const float4*)(rowb + 4*lane);
                    fma4(a, l0a.x, u4[0]); fma4(b, l0b.x, u4[0]);
                    fma4(a, l0a.y, u4[1]); fma4(b, l0b.y, u4[1]);
                    fma4(a, l0a.z, u4[2]); fma4(b, l0b.z, u4[2]);
                    fma4(a, l0a.w, u4[3]); fma4(b, l0b.w, u4[3]);
                    fma4(a, l1a.x, u4[4]); fma4(b, l1b.x, u4[4]);
                    fma4(a, l1a.y, u4[5]); fma4(b, l1b.y, u4[5]);
                    fma4(a, l1a.z, u4[6]); fma4(b, l1b.z, u4[6]);
                    fma4(a, l1a.w, u4[7]); fma4(b, l1b.w, u4[7]);
                    *(float4*)(rowa + 4*lane) = a;
                    if (hb) *(float4*)(rowb + 4*lane) = b;
                }
            }
        }
        __syncthreads();
    }

    // ---------- 5. combine & write real part of log psi ----------
    if (tid == 0) {
        float J = 0.0f;
        #pragma unroll
        for (int w = 0; w < 8; w++) J += sJ[w];
        out[s] = logabs + J;
    }
}

extern "C" void kernel_launch(void* const* d_in, const int* in_sizes, int n_in,
                              void* d_out, int out_size)
{
    // Identify inputs by element count (robust to metadata ordering):
    const float* n = nullptr;
    const float* M = nullptr;
    const float* W = nullptr;
    const float* b = nullptr;
    for (int i = 0; i < n_in; i++) {
        switch (in_sizes[i]) {
            case NB * NO:  n = (const float*)d_in[i]; break;
            case NO * NF:  M = (const float*)d_in[i]; break;
            case NO * HID: W = (const float*)d_in[i]; break;
            case HID:      b = (const float*)d_in[i]; break;
            default: break;
        }
    }
    float* out = (float*)d_out;   // (4096,) float32: real part of log psi

    cudaFuncSetAttribute(lnjs_kernel,
                         cudaFuncAttributeMaxDynamicSharedMemorySize,
                         SMEM_BYTES);

    lnjs_kernel<<<NB, NTHR, SMEM_BYTES>>>(n, M, W, b, out);
}

// round 14
// speedup vs baseline: 1.0510x; 1.0510x over previous
#include <cuda_runtime.h>
#include <cstdint>

#define NB    4096     // batch
#define NO    256      // orbitals
#define NF    128      // fermions
#define HID   512      // hidden
#define LDA   132      // padded row stride: 528B, 16B-aligned
#define NTHR  256
#define PB    8        // LU panel width
#define NPAN  (NF/PB)  // 16 panels

// Shared layout (floats): A | idx | perm | pcopy | wcnt(8) | sJ(8) | fsum(8)
#define SMEM_FLOATS (NF*LDA + NF + NF + NF + 8 + 8 + 8)
#define SMEM_BYTES  (SMEM_FLOATS * 4)

__device__ __forceinline__ void fma4(float4& a, float m, const float4& u) {
    a.x -= m * u.x; a.y -= m * u.y; a.z -= m * u.z; a.w -= m * u.w;
}

// Warp-synchronous panel factorization (executed by ONE warp, any warp id).
// Factors panel columns [kp, kp+PB) over logical rows >= kp, virtual pivoting
// via perm. Pivot argmax via shfl butterfly (known-good path).
// Accumulates log|pivot| into logabs on lane 0.
__device__ __forceinline__ void factor_panel(float* __restrict__ A,
                                             int*   __restrict__ perm,
                                             int kp, int lane, float& logabs)
{
    #pragma unroll
    for (int kk = 0; kk < PB; kk++) {
        const int k = kp + kk;
        float v = -1.0f; int vi = k;
        #pragma unroll
        for (int j = 0; j < 4; j++) {
            const int i = lane + 32*j;
            if (i >= k) {
                const float a = fabsf(A[perm[i]*LDA + k]);
                if (a > v) { v = a; vi = i; }
            }
        }
        #pragma unroll
        for (int o = 16; o; o >>= 1) {
            const float ov = __shfl_xor_sync(0xffffffffu, v,  o);
            const int   oi = __shfl_xor_sync(0xffffffffu, vi, o);
            if (ov > v) { v = ov; vi = oi; }
        }
        int pk = 0; float inv = 0.0f;
        if (lane == 0) {
            if (vi != k) { int t = perm[k]; perm[k] = perm[vi]; perm[vi] = t; }
            pk = perm[k];
            const float piv = A[pk*LDA + k];
            logabs += __logf(fabsf(piv));
            inv = 1.0f / piv;
        }
        __syncwarp();
        pk  = __shfl_sync(0xffffffffu, pk,  0);
        inv = __shfl_sync(0xffffffffu, inv, 0);

        const float* prow = A + pk*LDA + kp;
        #pragma unroll
        for (int j = 0; j < 4; j++) {
            const int i = lane + 32*j;
            if (i > k) {
                float* row = A + perm[i]*LDA;
                const float m = row[k] * inv;
                row[k] = m;
                #pragma unroll
                for (int c = 0; c < PB; c++)
                    if (c > kk) row[kp + c] -= m * prow[c];
            }
        }
        __syncwarp();
    }
}

__global__ void __launch_bounds__(NTHR, 3)
lnjs_kernel(const float* __restrict__ n_in,
            const float* __restrict__ M_in,
            const float* __restrict__ W_in,
            const float* __restrict__ b_in,
            float* __restrict__ out)
{
    extern __shared__ float sm[];
    float* A     = sm;
    int*   idx   = (int*)(sm + NF*LDA);
    int*   perm  = idx + NF;
    int*   pcopy = perm + NF;
    int*   wcnt  = pcopy + NF;
    float* sJ    = (float*)(wcnt + 8);
    float* fsum  = sJ + 8;

    const int s    = blockIdx.x;
    const int tid  = threadIdx.x;
    const int lane = tid & 31;
    const int wid  = tid >> 5;

    // ---------- 1. occupied indices via ballot prefix (NO == NTHR == 256) ----------
    const float nv = n_in[s*NO + tid];
    const bool occ = nv > 0.5f;
    const unsigned mask = __ballot_sync(0xffffffffu, occ);
    const int rank = __popc(mask & ((1u << lane) - 1u));
    if (lane == 0) { wcnt[wid] = __popc(mask); sJ[wid] = 0.0f; }
    __syncthreads();
    {
        int off = 0;
        #pragma unroll
        for (int w = 0; w < 8; w++) if (w < wid) off += wcnt[w];
        if (occ) idx[off + rank] = tid;
    }
    if (tid < NF) perm[tid] = tid;
    __syncthreads();

    // ---------- 2. load A = M[idx] into smem (float4) ----------
    #pragma unroll
    for (int e = tid; e < NF*32; e += NTHR) {
        const int r  = e >> 5;
        const int c4 = e & 31;
        ((float4*)(A + r*LDA))[c4] = ((const float4*)(M_in + (size_t)idx[r]*NF))[c4];
    }
    __syncthreads();

    // ---------- 3. prologue: warp 0 factors panel 0 | warps 1-7 do Jastrow ----------
    float logabs = 0.0f;   // lane 0 of each factor warp accumulates its panels

    if (wid == 0) {
        factor_panel(A, perm, 0, lane, logabs);
    } else {
        float jl = 0.0f;
        for (int h = tid - 32; h < HID; h += 224) {
            float acc = b_in[h];
            #pragma unroll 4
            for (int i = 0; i < NF; i++)
                acc += W_in[(size_t)idx[i]*HID + h];
            jl += tanhf(acc);
        }
        #pragma unroll
        for (int o = 16; o; o >>= 1) jl += __shfl_xor_sync(0xffffffffu, jl, o);
        if (lane == 0) sJ[wid] = jl;
    }
    __syncthreads();

    // ---------- 4. blocked LU, lookahead-1, rotating factor warp ----------
    for (int p = 0; p < NPAN - 1; p++) {
        const int kp = p * PB;
        const int pe = kp + PB;
        const int fw = (p + 1) & 7;           // factor warp for panel p+1

        // ======== phase A (all 8 warps) ========
        // snapshot perm[pe..NF) for phase-B wide warps (factor warp mutates perm in B)
        if (pe + tid < NF) pcopy[pe + tid] = perm[pe + tid];

        // strip update: cols [pe, pe+8), rows logical >= pe (on-the-fly TRSM)
        {
            const int ch = (lane & 1) * 4;   // half of the 8-col strip
            const int rs = lane >> 1;        // 0..15
            float4 u4s[PB];
            #pragma unroll
            for (int k2 = 0; k2 < PB; k2++) {
                const float* ur = A + perm[kp + k2]*LDA;
                float4 val = *(const float4*)(ur + pe + ch);
                #pragma unroll
                for (int j2 = 0; j2 < PB; j2++)
                    if (j2 < k2) fma4(val, ur[kp + j2], u4s[j2]);
                u4s[k2] = val;
            }
            const int i = pe + (wid << 4) + rs;   // 8 warps x 16 rows
            if (i < NF) {
                float* row = A + perm[i]*LDA;
                const float4 l0 = *(const float4*)(row + kp);
                const float4 l1 = *(const float4*)(row + kp + 4);
                float4 a = *(const float4*)(row + pe + ch);
                fma4(a, l0.x, u4s[0]); fma4(a, l0.y, u4s[1]);
                fma4(a, l0.z, u4s[2]); fma4(a, l0.w, u4s[3]);
                fma4(a, l1.x, u4s[4]); fma4(a, l1.y, u4s[5]);
                fma4(a, l1.z, u4s[6]); fma4(a, l1.w, u4s[7]);
                *(float4*)(row + pe + ch) = a;
            }
        }
        __syncthreads();

        // ======== phase B: factor warp fw factors panel p+1 | others wide update ========
        if (wid == fw) {
            factor_panel(A, perm, pe, lane, logabs);
        } else if (pe + PB < NF) {
            const int  ww  = (wid < fw) ? wid : wid - 1;   // 0..6 among wide warps
            const bool act = (4*lane >= pe + PB);
            float4 u4[PB];
            #pragma unroll
            for (int k2 = 0; k2 < PB; k2++) {
                const float* ur = A + perm[kp + k2]*LDA;
                float4 val = *(const float4*)(ur + 4*lane);
                #pragma unroll
                for (int j2 = 0; j2 < PB; j2++)
                    if (j2 < k2) fma4(val, ur[kp + j2], u4[j2]);
                u4[k2] = val;
            }
            for (int i = pe + ww; i < NF; i += 7) {
                float* row = A + pcopy[i]*LDA;
                const float4 l0 = *(const float4*)(row + kp);
                const float4 l1 = *(const float4*)(row + kp + 4);
                if (act) {
                    float4 a = *(const float4*)(row + 4*lane);
                    fma4(a, l0.x, u4[0]); fma4(a, l0.y, u4[1]);
                    fma4(a, l0.z, u4[2]); fma4(a, l0.w, u4[3]);
                    fma4(a, l1.x, u4[4]); fma4(a, l1.y, u4[5]);
                    fma4(a, l1.z, u4[6]); fma4(a, l1.w, u4[7]);
                    *(float4*)(row + 4*lane) = a;
                }
            }
        }
        __syncthreads();
    }

    // ---------- 5. combine & write real part of log psi ----------
    if (lane == 0) fsum[wid] = logabs;   // per-warp partial log|det|
    __syncthreads();
    if (tid == 0) {
        float r = 0.0f;
        #pragma unroll
        for (int w = 0; w < 8; w++) r += fsum[w] + sJ[w];
        out[s] = r;
    }
}

extern "C" void kernel_launch(void* const* d_in, const int* in_sizes, int n_in,
                              void* d_out, int out_size)
{
    // Identify inputs by element count (robust to metadata ordering):
    const float* n = nullptr;
    const float* M = nullptr;
    const float* W = nullptr;
    const float* b = nullptr;
    for (int i = 0; i < n_in; i++) {
        switch (in_sizes[i]) {
            case NB * NO:  n = (const float*)d_in[i]; break;
            case NO * NF:  M = (const float*)d_in[i]; break;
            case NO * HID: W = (const float*)d_in[i]; break;
            case HID:      b = (const float*)d_in[i]; break;
            default: break;
        }
    }
    float* out = (float*)d_out;   // (4096,) float32: real part of log psi

    cudaFuncSetAttribute(lnjs_kernel,
                         cudaFuncAttributeMaxDynamicSharedMemorySize,
                         SMEM_BYTES);

    lnjs_kernel<<<NB, NTHR, SMEM_BYTES>>>(n, M, W, b, out);
}

// round 15
// speedup vs baseline: 1.0788x; 1.0264x over previous
#include <cuda_runtime.h>
#include <cstdint>

#define NB    4096     // batch
#define NO    256      // orbitals
#define NF    128      // fermions
#define HID   512      // hidden
#define LDA   132      // padded row stride: 528B, 16B-aligned
#define NTHR  384      // 12 warps
#define NW    12
#define PB    8        // LU panel width
#define NPAN  (NF/PB)  // 16 panels

// Shared layout (floats): A | idx | perm | pcopy | wcnt(8) | sJ(NW) | fsum(NW)
#define SMEM_FLOATS (NF*LDA + NF + NF + NF + 8 + NW + NW)
#define SMEM_BYTES  (SMEM_FLOATS * 4)

__device__ __forceinline__ void fma4(float4& a, float m, const float4& u) {
    a.x -= m * u.x; a.y -= m * u.y; a.z -= m * u.z; a.w -= m * u.w;
}

// Warp-synchronous panel factorization (warp 0 only). Factors panel columns
// [kp, kp+PB) over logical rows >= kp, virtual pivoting via perm.
__device__ __forceinline__ void factor_panel(float* __restrict__ A,
                                             int*   __restrict__ perm,
                                             int kp, int lane, float& logabs)
{
    #pragma unroll
    for (int kk = 0; kk < PB; kk++) {
        const int k = kp + kk;
        float v = -1.0f; int vi = k;
        #pragma unroll
        for (int j = 0; j < 4; j++) {
            const int i = lane + 32*j;
            if (i >= k) {
                const float a = fabsf(A[perm[i]*LDA + k]);
                if (a > v) { v = a; vi = i; }
            }
        }
        #pragma unroll
        for (int o = 16; o; o >>= 1) {
            const float ov = __shfl_xor_sync(0xffffffffu, v,  o);
            const int   oi = __shfl_xor_sync(0xffffffffu, vi, o);
            if (ov > v) { v = ov; vi = oi; }
        }
        int pk = 0; float inv = 0.0f;
        if (lane == 0) {
            if (vi != k) { int t = perm[k]; perm[k] = perm[vi]; perm[vi] = t; }
            pk = perm[k];
            const float piv = A[pk*LDA + k];
            logabs += __logf(fabsf(piv));
            inv = 1.0f / piv;
        }
        __syncwarp();
        pk  = __shfl_sync(0xffffffffu, pk,  0);
        inv = __shfl_sync(0xffffffffu, inv, 0);

        const float* prow = A + pk*LDA + kp;
        #pragma unroll
        for (int j = 0; j < 4; j++) {
            const int i = lane + 32*j;
            if (i > k) {
                float* row = A + perm[i]*LDA;
                const float m = row[k] * inv;
                row[k] = m;
                #pragma unroll
                for (int c = 0; c < PB; c++)
                    if (c > kk) row[kp + c] -= m * prow[c];
            }
        }
        __syncwarp();
    }
}

__global__ void __launch_bounds__(NTHR, 3)
lnjs_kernel(const float* __restrict__ n_in,
            const float* __restrict__ M_in,
            const float* __restrict__ W_in,
            const float* __restrict__ b_in,
            float* __restrict__ out)
{
    extern __shared__ float sm[];
    float* A     = sm;
    int*   idx   = (int*)(sm + NF*LDA);
    int*   perm  = idx + NF;
    int*   pcopy = perm + NF;
    int*   wcnt  = pcopy + NF;
    float* sJ    = (float*)(wcnt + 8);
    float* fsum  = sJ + NW;

    const int s    = blockIdx.x;
    const int tid  = threadIdx.x;
    const int lane = tid & 31;
    const int wid  = tid >> 5;

    // ---------- 1. occupied indices via ballot prefix (warps 0-7 cover NO=256) ----------
    if (lane == 0) sJ[wid] = 0.0f;
    if (wid < 8) {
        const float nv = n_in[s*NO + tid];
        const bool occ = nv > 0.5f;
        const unsigned mask = __ballot_sync(0xffffffffu, occ);
        const int rank = __popc(mask & ((1u << lane) - 1u));
        if (lane == 0) wcnt[wid] = __popc(mask);
        __syncthreads();
        int off = 0;
        #pragma unroll
        for (int w = 0; w < 8; w++) if (w < wid) off += wcnt[w];
        if (occ) idx[off + rank] = tid;
    } else {
        __syncthreads();
    }
    if (tid < NF) perm[tid] = tid;
    __syncthreads();

    // ---------- 2. load A = M[idx] into smem (float4) ----------
    for (int e = tid; e < NF*32; e += NTHR) {
        const int r  = e >> 5;
        const int c4 = e & 31;
        ((float4*)(A + r*LDA))[c4] = ((const float4*)(M_in + (size_t)idx[r]*NF))[c4];
    }
    __syncthreads();

    // ---------- 3. prologue: warp 0 factors panel 0 | warps 1-11 do Jastrow ----------
    float logabs = 0.0f;   // warp 0 lane 0 accumulates

    if (wid == 0) {
        factor_panel(A, perm, 0, lane, logabs);
    } else {
        float jl = 0.0f;
        for (int h = tid - 32; h < HID; h += NTHR - 32) {
            float acc = b_in[h];
            #pragma unroll 4
            for (int i = 0; i < NF; i++)
                acc += W_in[(size_t)idx[i]*HID + h];
            jl += tanhf(acc);
        }
        #pragma unroll
        for (int o = 16; o; o >>= 1) jl += __shfl_xor_sync(0xffffffffu, jl, o);
        if (lane == 0) sJ[wid] = jl;
    }
    __syncthreads();

    // ---------- 4. blocked LU, lookahead-1 ----------
    for (int p = 0; p < NPAN - 1; p++) {
        const int kp = p * PB;
        const int pe = kp + PB;

        // ======== phase A (all 12 warps) ========
        // snapshot perm[pe..NF) for phase-B wide warps (warp 0 mutates perm in B)
        if (pe + tid < NF) pcopy[pe + tid] = perm[pe + tid];

        // strip update: cols [pe, pe+8), rows logical >= pe (on-the-fly TRSM)
        {
            const int ch = (lane & 1) * 4;   // half of the 8-col strip
            const int rs = lane >> 1;        // 0..15
            float4 u4s[PB];
            #pragma unroll
            for (int k2 = 0; k2 < PB; k2++) {
                const float* ur = A + perm[kp + k2]*LDA;
                float4 val = *(const float4*)(ur + pe + ch);
                #pragma unroll
                for (int j2 = 0; j2 < PB; j2++)
                    if (j2 < k2) fma4(val, ur[kp + j2], u4s[j2]);
                u4s[k2] = val;
            }
            const int i = pe + (wid << 4) + rs;   // 12 warps x 16 rows = 192 slots
            if (i < NF) {
                float* row = A + perm[i]*LDA;
                const float4 l0 = *(const float4*)(row + kp);
                const float4 l1 = *(const float4*)(row + kp + 4);
                float4 a = *(const float4*)(row + pe + ch);
                fma4(a, l0.x, u4s[0]); fma4(a, l0.y, u4s[1]);
                fma4(a, l0.z, u4s[2]); fma4(a, l0.w, u4s[3]);
                fma4(a, l1.x, u4s[4]); fma4(a, l1.y, u4s[5]);
                fma4(a, l1.z, u4s[6]); fma4(a, l1.w, u4s[7]);
                *(float4*)(row + pe + ch) = a;
            }
        }
        __syncthreads();

        // ======== phase B: warp 0 factors panel p+1 | warps 1-11 wide update ========
        if (wid == 0) {
            factor_panel(A, perm, pe, lane, logabs);
        } else if (pe + PB < NF) {
            const bool act = (4*lane >= pe + PB);
            float4 u4[PB];
            #pragma unroll
            for (int k2 = 0; k2 < PB; k2++) {
                const float* ur = A + perm[kp + k2]*LDA;
                float4 val = *(const float4*)(ur + 4*lane);
                #pragma unroll
                for (int j2 = 0; j2 < PB; j2++)
                    if (j2 < k2) fma4(val, ur[kp + j2], u4[j2]);
                u4[k2] = val;
            }
            for (int i = pe + (wid - 1); i < NF; i += NW - 1) {
                float* row = A + pcopy[i]*LDA;
                const float4 l0 = *(const float4*)(row + kp);
                const float4 l1 = *(const float4*)(row + kp + 4);
                if (act) {
                    float4 a = *(const float4*)(row + 4*lane);
                    fma4(a, l0.x, u4[0]); fma4(a, l0.y, u4[1]);
                    fma4(a, l0.z, u4[2]); fma4(a, l0.w, u4[3]);
                    fma4(a, l1.x, u4[4]); fma4(a, l1.y, u4[5]);
                    fma4(a, l1.z, u4[6]); fma4(a, l1.w, u4[7]);
                    *(float4*)(row + 4*lane) = a;
                }
            }
        }
        __syncthreads();
    }

    // ---------- 5. combine & write real part of log psi ----------
    if (lane == 0) fsum[wid] = logabs;   // nonzero only for warp 0
    __syncthreads();
    if (tid == 0) {
        float r = 0.0f;
        #pragma unroll
        for (int w = 0; w < NW; w++) r += fsum[w] + sJ[w];
        out[s] = r;
    }
}

extern "C" void kernel_launch(void* const* d_in, const int* in_sizes, int n_in,
                              void* d_out, int out_size)
{
    // Identify inputs by element count (robust to metadata ordering):
    const float* n = nullptr;
    const float* M = nullptr;
    const float* W = nullptr;
    const float* b = nullptr;
    for (int i = 0; i < n_in; i++) {
        switch (in_sizes[i]) {
            case NB * NO:  n = (const float*)d_in[i]; break;
            case NO * NF:  M = (const float*)d_in[i]; break;
            case NO * HID: W = (const float*)d_in[i]; break;
            case HID:      b = (const float*)d_in[i]; break;
            default: break;
        }
    }
    float* out = (float*)d_out;   // (4096,) float32: real part of log psi

    cudaFuncSetAttribute(lnjs_kernel,
                         cudaFuncAttributeMaxDynamicSharedMemorySize,
                         SMEM_BYTES);

    lnjs_kernel<<<NB, NTHR, SMEM_BYTES>>>(n, M, W, b, out);
}

// round 17
// speedup vs baseline: 1.3804x; 1.2795x over previous
#include <cuda_runtime.h>
#include <cstdint>

#define NB    4096     // batch
#define NO    256      // orbitals
#define NF    128      // fermions
#define HID   512      // hidden
#define LDA   132      // padded row stride: 528B, 16B-aligned
#define NTHR  256
#define PB    8        // LU panel width
#define NPAN  (NF/PB)  // 16 panels

// Shared layout (floats): A | idx | perm | iperm | pcopy | wcnt(8) | sJ(8) | fsum(8)
#define SMEM_FLOATS (NF*LDA + NF + NF + NF + NF + 8 + 8 + 8)
#define SMEM_BYTES  (SMEM_FLOATS * 4)

__device__ __forceinline__ void fma4(float4& a, float m, const float4& u) {
    a.x -= m * u.x; a.y -= m * u.y; a.z -= m * u.z; a.w -= m * u.w;
}

// Register-resident panel factorization (factor warp only).
// Panel cols [kp,kp+PB) live in pnl[slot][c] (lane owns physical rows
// lane+32*slot). Pivot steps run on registers + shfl; smem is touched only
// for load, writeback, and perm/iperm bookkeeping (lane 0, off-path).
__device__ __forceinline__ void factor_panel_reg(float* __restrict__ A,
                                                 int*   __restrict__ perm,
                                                 int*   __restrict__ iperm,
                                                 int kp, int lane, float& logabs)
{
    float pnl[4][8];
    unsigned cmask = 0u;
    #pragma unroll
    for (int sl = 0; sl < 4; sl++) {
        const int r = lane + 32*sl;
        const float4 t0 = *(const float4*)(A + r*LDA + kp);
        const float4 t1 = *(const float4*)(A + r*LDA + kp + 4);
        pnl[sl][0]=t0.x; pnl[sl][1]=t0.y; pnl[sl][2]=t0.z; pnl[sl][3]=t0.w;
        pnl[sl][4]=t1.x; pnl[sl][5]=t1.y; pnl[sl][6]=t1.z; pnl[sl][7]=t1.w;
        if (iperm[r] >= kp) cmask |= (1u << sl);   // still a candidate row
    }

    #pragma unroll
    for (int kk = 0; kk < PB; kk++) {
        // argmax |pnl[sl][kk]| over candidate rows (slots first, then lanes)
        float v = -1.0f; int sl = 0;
        #pragma unroll
        for (int s2 = 0; s2 < 4; s2++) {
            const float a = (cmask >> s2) & 1u ? fabsf(pnl[s2][kk]) : -1.0f;
            if (a > v) { v = a; sl = s2; }
        }
        int li = lane;
        #pragma unroll
        for (int o = 16; o; o >>= 1) {
            const float ov  = __shfl_xor_sync(0xffffffffu, v,  o);
            const int   oli = __shfl_xor_sync(0xffffffffu, li, o);
            const int   osl = __shfl_xor_sync(0xffffffffu, sl, o);
            if (ov > v) { v = ov; li = oli; sl = osl; }
        }
        li = __shfl_sync(0xffffffffu, li, 0);   // lane 0's argmax is canonical
        sl = __shfl_sync(0xffffffffu, sl, 0);

        // broadcast pivot row columns kk..7 (sl is warp-uniform -> selects)
        float pr[8];
        #pragma unroll
        for (int c = 0; c < 8; c++) {
            if (c >= kk) {
                const float x = (sl == 0) ? pnl[0][c] :
                                (sl == 1) ? pnl[1][c] :
                                (sl == 2) ? pnl[2][c] : pnl[3][c];
                pr[c] = __shfl_sync(0xffffffffu, x, li);
            }
        }
        const float piv = pr[kk];
        const float inv = 1.0f / piv;

        if (lane == 0) {
            logabs += __logf(fabsf(piv));
            const int rstar = li + 32*sl;       // physical pivot row
            const int k  = kp + kk;
            const int vi = iperm[rstar];        // its logical index
            const int t  = perm[k];
            perm[k] = rstar; perm[vi] = t;
            iperm[rstar] = k; iperm[t] = vi;
        }
        if (lane == li) cmask &= ~(1u << sl);   // retire pivot row

        // rank-1 update of remaining candidate rows (registers only)
        #pragma unroll
        for (int s2 = 0; s2 < 4; s2++) {
            if ((cmask >> s2) & 1u) {
                const float m = pnl[s2][kk] * inv;
                pnl[s2][kk] = m;
                #pragma unroll
                for (int c = 0; c < 8; c++)
                    if (c > kk) pnl[s2][c] -= m * pr[c];
            }
        }
    }

    // writeback (cols [kp,kp+8) of all rows; non-candidates unchanged)
    #pragma unroll
    for (int sl = 0; sl < 4; sl++) {
        const int r = lane + 32*sl;
        *(float4*)(A + r*LDA + kp)     = make_float4(pnl[sl][0], pnl[sl][1], pnl[sl][2], pnl[sl][3]);
        *(float4*)(A + r*LDA + kp + 4) = make_float4(pnl[sl][4], pnl[sl][5], pnl[sl][6], pnl[sl][7]);
    }
}

__global__ void __launch_bounds__(NTHR, 3)
lnjs_kernel(const float* __restrict__ n_in,
            const float* __restrict__ M_in,
            const float* __restrict__ W_in,
            const float* __restrict__ b_in,
            float* __restrict__ out)
{
    extern __shared__ float sm[];
    float* A     = sm;
    int*   idx   = (int*)(sm + NF*LDA);
    int*   perm  = idx + NF;
    int*   iperm = perm + NF;
    int*   pcopy = iperm + NF;
    int*   wcnt  = pcopy + NF;
    float* sJ    = (float*)(wcnt + 8);
    float* fsum  = sJ + 8;

    const int s    = blockIdx.x;
    const int tid  = threadIdx.x;
    const int lane = tid & 31;
    const int wid  = tid >> 5;

    // ---------- 1. occupied indices via ballot prefix (NO == NTHR == 256) ----------
    const float nv = n_in[s*NO + tid];
    const bool occ = nv > 0.5f;
    const unsigned mask = __ballot_sync(0xffffffffu, occ);
    const int rank = __popc(mask & ((1u << lane) - 1u));
    if (lane == 0) { wcnt[wid] = __popc(mask); sJ[wid] = 0.0f; }
    __syncthreads();
    {
        int off = 0;
        #pragma unroll
        for (int w = 0; w < 8; w++) if (w < wid) off += wcnt[w];
        if (occ) idx[off + rank] = tid;
    }
    if (tid < NF) { perm[tid] = tid; iperm[tid] = tid; }
    __syncthreads();

    // ---------- 2. load A = M[idx] into smem (float4) ----------
    #pragma unroll
    for (int e = tid; e < NF*32; e += NTHR) {
        const int r  = e >> 5;
        const int c4 = e & 31;
        ((float4*)(A + r*LDA))[c4] = ((const float4*)(M_in + (size_t)idx[r]*NF))[c4];
    }
    __syncthreads();

    // ---------- 3. prologue: warp 0 factors panel 0 | warps 1-7 do Jastrow ----------
    float logabs = 0.0f;   // warp 0 lane 0 accumulates

    if (wid == 0) {
        factor_panel_reg(A, perm, iperm, 0, lane, logabs);
    } else {
        float jl = 0.0f;
        for (int h = tid - 32; h < HID; h += NTHR - 32) {
            float acc = b_in[h];
            #pragma unroll 4
            for (int i = 0; i < NF; i++)
                acc += W_in[(size_t)idx[i]*HID + h];
            jl += tanhf(acc);
        }
        #pragma unroll
        for (int o = 16; o; o >>= 1) jl += __shfl_xor_sync(0xffffffffu, jl, o);
        if (lane == 0) sJ[wid] = jl;
    }
    __syncthreads();

    // ---------- 4. blocked LU, lookahead-1 ----------
    for (int p = 0; p < NPAN - 1; p++) {
        const int kp = p * PB;
        const int pe = kp + PB;

        // ======== phase A (all 8 warps) ========
        // snapshot perm[pe..NF) for phase-B wide warps (warp 0 mutates perm in B)
        if (pe + tid < NF) pcopy[pe + tid] = perm[pe + tid];

        // strip update: cols [pe, pe+8), rows logical >= pe (on-the-fly TRSM)
        {
            const int ch = (lane & 1) * 4;   // half of the 8-col strip
            const int rs = lane >> 1;        // 0..15
            float4 u4s[PB];
            #pragma unroll
            for (int k2 = 0; k2 < PB; k2++) {
                const float* ur = A + perm[kp + k2]*LDA;
                float4 val = *(const float4*)(ur + pe + ch);
                #pragma unroll
                for (int j2 = 0; j2 < PB; j2++)
                    if (j2 < k2) fma4(val, ur[kp + j2], u4s[j2]);
                u4s[k2] = val;
            }
            const int i = pe + (wid << 4) + rs;   // 8 warps x 16 rows
            if (i < NF) {
                float* row = A + perm[i]*LDA;
                const float4 l0 = *(const float4*)(row + kp);
                const float4 l1 = *(const float4*)(row + kp + 4);
                float4 a = *(const float4*)(row + pe + ch);
                fma4(a, l0.x, u4s[0]); fma4(a, l0.y, u4s[1]);
                fma4(a, l0.z, u4s[2]); fma4(a, l0.w, u4s[3]);
                fma4(a, l1.x, u4s[4]); fma4(a, l1.y, u4s[5]);
                fma4(a, l1.z, u4s[6]); fma4(a, l1.w, u4s[7]);
                *(float4*)(row + pe + ch) = a;
            }
        }
        __syncthreads();

        // ======== phase B: warp 0 factors panel p+1 | warps 1-7 wide update ========
        if (wid == 0) {
            factor_panel_reg(A, perm, iperm, pe, lane, logabs);
        } else if (pe + PB < NF) {
            const bool act = (4*lane >= pe + PB);
            float4 u4[PB];
            #pragma unroll
            for (int k2 = 0; k2 < PB; k2++) {
                const float* ur = A + perm[kp + k2]*LDA;
                float4 val = *(const float4*)(ur + 4*lane);
                #pragma unroll
                for (int j2 = 0; j2 < PB; j2++)
                    if (j2 < k2) fma4(val, ur[kp + j2], u4[j2]);
                u4[k2] = val;
            }
            for (int i = pe + (wid - 1); i < NF; i += 7) {
                float* row = A + pcopy[i]*LDA;
                const float4 l0 = *(const float4*)(row + kp);
                const float4 l1 = *(const float4*)(row + kp + 4);
                if (act) {
                    float4 a = *(const float4*)(row + 4*lane);
                    fma4(a, l0.x, u4[0]); fma4(a, l0.y, u4[1]);
                    fma4(a, l0.z, u4[2]); fma4(a, l0.w, u4[3]);
                    fma4(a, l1.x, u4[4]); fma4(a, l1.y, u4[5]);
                    fma4(a, l1.z, u4[6]); fma4(a, l1.w, u4[7]);
                    *(float4*)(row + 4*lane) = a;
                }
            }
        }
        __syncthreads();
    }

    // ---------- 5. combine & write real part of log psi ----------
    if (lane == 0) fsum[wid] = logabs;   // nonzero only for warp 0
    __syncthreads();
    if (tid == 0) {
        float r = 0.0f;
        #pragma unroll
        for (int w = 0; w < 8; w++) r += fsum[w] + sJ[w];
        out[s] = r;
    }
}

extern "C" void kernel_launch(void* const* d_in, const int* in_sizes, int n_in,
                              void* d_out, int out_size)
{
    // Identify inputs by element count (robust to metadata ordering):
    const float* n = nullptr;
    const float* M = nullptr;
    const float* W = nullptr;
    const float* b = nullptr;
    for (int i = 0; i < n_in; i++) {
        switch (in_sizes[i]) {
            case NB * NO:  n = (const float*)d_in[i]; break;
            case NO * NF:  M = (const float*)d_in[i]; break;
            case NO * HID: W = (const float*)d_in[i]; break;
            case HID:      b = (const float*)d_in[i]; break;
            default: break;
        }
    }
    float* out = (float*)d_out;   // (4096,) float32: real part of log psi

    cudaFuncSetAttribute(lnjs_kernel,
                         cudaFuncAttributeMaxDynamicSharedMemorySize,
                         SMEM_BYTES);

    lnjs_kernel<<<NB, NTHR, SMEM_BYTES>>>(n, M, W, b, out);
}